// round 16
// baseline (speedup 1.0000x reference)
#include <cuda_runtime.h>
#include <cuda_fp16.h>
#include <cstdint>
#include <cstddef>

// Problem constants
#define Bz 32
#define Sz 2048
#define Hz 1024
#define Uz 1024
#define MTOT 65536   // B*S

// Scratch (device globals — no runtime allocation)
__device__ __align__(128) __half g_W1h[Uz * Hz];          // W1^T: [u][h] fp16
__device__ __align__(128) __half g_Xh[(size_t)MTOT * Hz]; // X fp16: [m][h]
__device__ float g_ph[Bz * Uz];                            // W1_b + W2_b + h @ W2
__device__ float g_part[8][MTOT];                          // per-octant partial scores

// ---------------- PTX helpers (baseline compute_103 only) ----------------
__device__ __forceinline__ uint32_t smem_u32(const void* p) {
    uint32_t a;
    asm("{ .reg .u64 t; cvta.to.shared.u64 t, %1; cvt.u32.u64 %0, t; }" : "=r"(a) : "l"(p));
    return a;
}

#define LDSM_X4(r0, r1, r2, r3, addr)                                        \
    asm volatile("ldmatrix.sync.aligned.m8n8.x4.shared.b16 {%0,%1,%2,%3}, [%4];" \
        : "=r"(r0), "=r"(r1), "=r"(r2), "=r"(r3) : "r"(addr))

#define MMA16816(c, a, b0v, b1v)                                             \
    asm volatile("mma.sync.aligned.m16n8k16.row.col.f32.f16.f16.f32 "        \
        "{%0,%1,%2,%3}, {%4,%5,%6,%7}, {%8,%9}, {%0,%1,%2,%3};"              \
        : "+f"((c)[0]), "+f"((c)[1]), "+f"((c)[2]), "+f"((c)[3])             \
        : "r"((a)[0]), "r"((a)[1]), "r"((a)[2]), "r"((a)[3]),                \
          "r"(b0v), "r"(b1v))

__device__ __forceinline__ uint32_t sw128(uint32_t off) {
    return off ^ ((off >> 3) & 0x70);
}

// hardware tanh approximation (MUFU; error sub-dominant to fp16 quantization)
__device__ __forceinline__ float tanh_fast(float x) {
    float y;
    asm("tanh.approx.f32 %0, %1;" : "=f"(y) : "f"(x));
    return y;
}

// ---------------- fused prep: X convert | W1 transpose | ph init ---------
// blocks [0, 2048):    X fp32 -> fp16 streaming convert (DRAM-bound, ~55us)
// blocks [2048, 3072): W1 [H,U] fp32 -> g_W1h [U,H] fp16 (rides in X window)
// blocks [3072, 3200): ph init (W1_b + W2_b)
__global__ void __launch_bounds__(256)
k_prep(const float* __restrict__ X, const float* __restrict__ W1,
       const float* __restrict__ W1b, const float* __restrict__ W2b) {
    __shared__ float t[32][33];
    const int bid = blockIdx.x;
    const int tid = threadIdx.x;

    if (bid < 2048) {
        size_t i = (size_t)bid * 256 + tid;   // float4 index
        const size_t stride = (size_t)2048 * 256;
        const size_t total = (size_t)MTOT * Hz / 4;
        for (; i < total; i += stride) {
            float4 v = *reinterpret_cast<const float4*>(X + i * 4);
            __half2 h0 = __floats2half2_rn(v.x, v.y);
            __half2 h1 = __floats2half2_rn(v.z, v.w);
            uint2 pk = make_uint2(*reinterpret_cast<uint32_t*>(&h0),
                                  *reinterpret_cast<uint32_t*>(&h1));
            *reinterpret_cast<uint2*>(g_Xh + i * 4) = pk;
        }
    } else if (bid < 3072) {
        const int b2 = bid - 2048;            // 0..1023
        const int u0 = (b2 & 31) * 32, h0 = (b2 >> 5) * 32;
        const int tx = tid & 31, ty = tid >> 5;   // 32 x 8
        #pragma unroll
        for (int j = 0; j < 32; j += 8)
            t[ty + j][tx] = W1[(size_t)(h0 + ty + j) * Uz + u0 + tx];
        __syncthreads();
        #pragma unroll
        for (int j = 0; j < 32; j += 8)
            g_W1h[(size_t)(u0 + ty + j) * Hz + h0 + tx] = __float2half(t[tx][ty + j]);
    } else {
        const int i = (bid - 3072) * 256 + tid;   // 0..32767
        const int u = i & (Uz - 1);
        g_ph[i] = W1b[u] + W2b[u];
    }
}

// ph[b][u] += sum_h lh[b][h] * W2[h][u]   (u-blocks of 64, h-slices of 16)
__global__ void k_ph(const float* __restrict__ lh, const float* __restrict__ W2) {
    __shared__ float lh_s[32][16];
    int u0 = blockIdx.x * 64, h0 = blockIdx.y * 16;
    int tid = threadIdx.x;
    for (int idx = tid; idx < 512; idx += 256) {
        int bb = idx >> 4, hh = idx & 15;
        lh_s[bb][hh] = lh[bb * Hz + h0 + hh];
    }
    __syncthreads();
    int u = u0 + (tid & 63);
    int bh = (tid >> 6) * 8;     // 4 groups x 8 batches
    float acc[8];
    #pragma unroll
    for (int i = 0; i < 8; ++i) acc[i] = 0.f;
    #pragma unroll
    for (int hh = 0; hh < 16; ++hh) {
        float w = W2[(size_t)(h0 + hh) * Uz + u];
        #pragma unroll
        for (int i = 0; i < 8; ++i) acc[i] += lh_s[bh + i][hh] * w;
    }
    #pragma unroll
    for (int i = 0; i < 8; ++i) atomicAdd(&g_ph[(bh + i) * Uz + u], acc[i]);
}

// ---------------- fused main: GEMM(HMMA) + tanh + V-dot ----------------
// Grid (8, 512): blockIdx.x = n-octant (128 cols), blockIdx.y = m-tile (128).
// 128 threads / 4 warps per CTA, warp grid (2m, 2n), warp tile 64 x 64.
// smem 100352 B -> TWO CTAs co-resident per SM: while one CTA barriers /
// runs its epilogue, the other's MMAs keep the tensor pipe busy.
// K = 1024 in 16 slices of 64, 3-stage cp.async pipeline.
// Final partial score is plain-stored to g_part[oct] (no global atomics).
// SMEM map (bytes):
//   [0   .. 512)     score_s (128 f32)
//   [512 .. 1024)    ph_s    (128 f32)
//   [1024.. 1536)    v_s     (128 f32)
//   [2048.. 51200)   X fp16  3 stages x [128 x 64] SW128 (16KB/stage)
//   [51200..100352)  W fp16  3 stages x [128 x 64] SW128 (16KB/stage)
#define SMEM_MAIN 100352

__global__ void __launch_bounds__(128, 2)
k_main(const float* __restrict__ Vw) {
    extern __shared__ char smem[];
    const uint32_t sb = smem_u32(smem);
    float* score_s = reinterpret_cast<float*>(smem);
    float* ph_s = reinterpret_cast<float*>(smem + 512);
    float* v_s = reinterpret_cast<float*>(smem + 1024);
    const uint32_t XS = sb + 2048;
    const uint32_t WS = sb + 51200;

    const int tid = threadIdx.x;
    const int wid = tid >> 5, l = tid & 31;
    const int wm = wid & 1, wn = wid >> 1;     // 2m x 2n warp grid
    const int m0 = blockIdx.y * 128;
    const int n0 = blockIdx.x * 128;
    const int b = m0 >> 11;                    // batch (2048 rows each)

    score_s[tid] = 0.f;
    ph_s[tid] = g_ph[b * Uz + n0 + tid];
    v_s[tid] = Vw[n0 + tid];

    // ldmatrix lane-invariant offset pieces
    const uint32_t a_row = (uint32_t)(wm * 64 + (l & 15));
    const uint32_t a_k16 = (uint32_t)(((l >> 4) & 1) * 16);
    const uint32_t b_row = (uint32_t)(wn * 64 + ((l >> 4) & 1) * 8 + (l & 7));
    const uint32_t b_k16 = (uint32_t)(((l >> 3) & 1) * 16);

    // cp.async pieces: X 1024 + W 1024 chunks of 16B, 128 threads
    const int cp_r = tid >> 3;            // row 0..15 base
    const int cp_c = tid & 7;             // 16B column 0..7

    float acc[4][8][4];
    #pragma unroll
    for (int mb = 0; mb < 4; ++mb)
        #pragma unroll
        for (int nb = 0; nb < 8; ++nb)
            #pragma unroll
            for (int i = 0; i < 4; ++i) acc[mb][nb][i] = 0.f;

    // ---- issue cp.async loads for slice s into stage s%3 ----
    auto load_slice = [&](int s) {
        const int st = s % 3;
        const int k0 = s * 64;
        const uint32_t xdst = XS + st * 16384;
        const uint32_t wdst = WS + st * 16384;
        const __half* xsrc = g_Xh + (size_t)m0 * Hz + k0;
        const __half* wsrc = g_W1h + (size_t)n0 * Hz + k0;
        #pragma unroll
        for (int i = 0; i < 8; ++i) {         // 128 rows each, 16 per pass
            int r = cp_r + i * 16;
            uint32_t dso = sw128((uint32_t)(r * 128 + cp_c * 16));
            size_t gx = __cvta_generic_to_global(xsrc + (size_t)r * Hz + cp_c * 8);
            size_t gw = __cvta_generic_to_global(wsrc + (size_t)r * Hz + cp_c * 8);
            asm volatile("cp.async.cg.shared.global [%0], [%1], 16;"
                         :: "r"(xdst + dso), "l"(gx));
            asm volatile("cp.async.cg.shared.global [%0], [%1], 16;"
                         :: "r"(wdst + dso), "l"(gw));
        }
        asm volatile("cp.async.commit_group;");
    };

    // prologue: fill 2 of 3 stages
    load_slice(0);
    load_slice(1);

    for (int s = 0; s < 16; ++s) {
        if (s < 15) asm volatile("cp.async.wait_group 1;");
        else        asm volatile("cp.async.wait_group 0;");
        __syncthreads();   // publish stage s; stage (s+2)%3 free

        if (s + 2 < 16) load_slice(s + 2);

        const uint32_t xb = XS + (s % 3) * 16384;
        const uint32_t wb = WS + (s % 3) * 16384;

        #pragma unroll
        for (int kk = 0; kk < 4; ++kk) {      // four k16 steps per 64-k slice
            uint32_t fa[4][4], fb[4][4];
            #pragma unroll
            for (int mb = 0; mb < 4; ++mb) {
                uint32_t off = (a_row + mb * 16) * 128 + kk * 32 + a_k16;
                LDSM_X4(fa[mb][0], fa[mb][1], fa[mb][2], fa[mb][3],
                        xb + sw128(off));
            }
            #pragma unroll
            for (int p = 0; p < 4; ++p) {
                uint32_t off = (b_row + p * 16) * 128 + kk * 32 + b_k16;
                LDSM_X4(fb[p][0], fb[p][1], fb[p][2], fb[p][3],
                        wb + sw128(off));
            }
            #pragma unroll
            for (int mb = 0; mb < 4; ++mb)
                #pragma unroll
                for (int nb = 0; nb < 8; ++nb)
                    MMA16816(acc[mb][nb], fa[mb],
                             fb[nb >> 1][(nb & 1) * 2],
                             fb[nb >> 1][(nb & 1) * 2 + 1]);
        }
    }

    // ---- epilogue: tanh(acc + ph) * v, reduce over the 128 n-cols ----
    const int t = l & 3, g = l >> 2;
    #pragma unroll
    for (int mb = 0; mb < 4; ++mb) {
        float rs0 = 0.f, rs1 = 0.f;
        #pragma unroll
        for (int nb = 0; nb < 8; ++nb) {
            int nl = wn * 64 + nb * 8 + t * 2;
            float p0 = ph_s[nl], v0 = v_s[nl];
            float p1 = ph_s[nl + 1], v1 = v_s[nl + 1];
            rs0 += tanh_fast(acc[mb][nb][0] + p0) * v0
                 + tanh_fast(acc[mb][nb][1] + p1) * v1;
            rs1 += tanh_fast(acc[mb][nb][2] + p0) * v0
                 + tanh_fast(acc[mb][nb][3] + p1) * v1;
        }
        rs0 += __shfl_xor_sync(0xffffffffu, rs0, 1);
        rs0 += __shfl_xor_sync(0xffffffffu, rs0, 2);
        rs1 += __shfl_xor_sync(0xffffffffu, rs1, 1);
        rs1 += __shfl_xor_sync(0xffffffffu, rs1, 2);
        if (t == 0) {
            int r0 = wm * 64 + mb * 16 + g;
            atomicAdd(&score_s[r0], rs0);
            atomicAdd(&score_s[r0 + 8], rs1);
        }
    }
    __syncthreads();

    g_part[blockIdx.x][m0 + tid] = score_s[tid];
}

// ---------------- softmax over S per batch (sums 8 octant partials) ------
__global__ void k_softmax(float* __restrict__ out) {
    __shared__ float red[256];
    int b = blockIdx.x, tid = threadIdx.x;  // 256 threads, 8 elems each
    float v[8];
    float mx = -1e30f;
    #pragma unroll
    for (int i = 0; i < 8; ++i) {
        int s = b * Sz + tid + i * 256;
        float x = 0.f;
        #pragma unroll
        for (int o = 0; o < 8; ++o) x += g_part[o][s];
        v[i] = x;
        mx = fmaxf(mx, x);
    }
    red[tid] = mx;
    __syncthreads();
    for (int o = 128; o > 0; o >>= 1) {
        if (tid < o) red[tid] = fmaxf(red[tid], red[tid + o]);
        __syncthreads();
    }
    mx = red[0];
    __syncthreads();
    float sum = 0.f;
    #pragma unroll
    for (int i = 0; i < 8; ++i) { v[i] = expf(v[i] - mx); sum += v[i]; }
    red[tid] = sum;
    __syncthreads();
    for (int o = 128; o > 0; o >>= 1) {
        if (tid < o) red[tid] += red[tid + o];
        __syncthreads();
    }
    float tot = red[0];
    #pragma unroll
    for (int i = 0; i < 8; ++i)
        out[b * Sz + tid + i * 256] = v[i] / tot;
}

// ---------------- launch ----------------
extern "C" void kernel_launch(void* const* d_in, const int* in_sizes, int n_in,
                              void* d_out, int out_size) {
    const float* enc = (const float*)d_in[0];   // [B,S,H]
    const float* lh  = (const float*)d_in[1];   // [B,H]
    const float* W1  = (const float*)d_in[2];   // [H,U]
    const float* W1b = (const float*)d_in[3];   // [U]
    const float* W2  = (const float*)d_in[4];   // [H,U]
    const float* W2b = (const float*)d_in[5];   // [U]
    const float* Vw  = (const float*)d_in[6];   // [U,1]
    float* out = (float*)d_out;                  // [B,S,1]

    cudaFuncSetAttribute(k_main, cudaFuncAttributeMaxDynamicSharedMemorySize, SMEM_MAIN);

    k_prep<<<3200, 256>>>(enc, W1, W1b, W2b);
    k_ph<<<dim3(16, 64), 256>>>(lh, W2);
    k_main<<<dim3(8, 512), 128, SMEM_MAIN>>>(Vw);
    k_softmax<<<Bz, 256>>>(out);
}

// round 17
// speedup vs baseline: 1.0076x; 1.0076x over previous
#include <cuda_runtime.h>
#include <cuda_fp16.h>
#include <cstdint>
#include <cstddef>

// Problem constants
#define Bz 32
#define Sz 2048
#define Hz 1024
#define Uz 1024
#define MTOT 65536   // B*S

// Scratch (device globals — no runtime allocation)
__device__ __align__(128) __half g_W1h[Uz * Hz];          // W1^T: [u][h] fp16
__device__ __align__(128) __half g_Xh[(size_t)MTOT * Hz]; // X fp16: [m][h]
__device__ float g_ph[Bz * Uz];                            // W1_b + W2_b + h @ W2
__device__ float g_score[MTOT];                            // pre-softmax scores

// ---------------- PTX helpers (baseline compute_103 only) ----------------
__device__ __forceinline__ uint32_t smem_u32(const void* p) {
    uint32_t a;
    asm("{ .reg .u64 t; cvta.to.shared.u64 t, %1; cvt.u32.u64 %0, t; }" : "=r"(a) : "l"(p));
    return a;
}

#define LDSM_X4(r0, r1, r2, r3, addr)                                        \
    asm volatile("ldmatrix.sync.aligned.m8n8.x4.shared.b16 {%0,%1,%2,%3}, [%4];" \
        : "=r"(r0), "=r"(r1), "=r"(r2), "=r"(r3) : "r"(addr))

#define MMA16816(c, a, b0v, b1v)                                             \
    asm volatile("mma.sync.aligned.m16n8k16.row.col.f32.f16.f16.f32 "        \
        "{%0,%1,%2,%3}, {%4,%5,%6,%7}, {%8,%9}, {%0,%1,%2,%3};"              \
        : "+f"((c)[0]), "+f"((c)[1]), "+f"((c)[2]), "+f"((c)[3])             \
        : "r"((a)[0]), "r"((a)[1]), "r"((a)[2]), "r"((a)[3]),                \
          "r"(b0v), "r"(b1v))

__device__ __forceinline__ uint32_t sw128(uint32_t off) {
    return off ^ ((off >> 3) & 0x70);
}

// hardware tanh approximation (MUFU; error sub-dominant to fp16 quantization)
__device__ __forceinline__ float tanh_fast(float x) {
    float y;
    asm("tanh.approx.f32 %0, %1;" : "=f"(y) : "f"(x));
    return y;
}

// ---------------- fused prep: X convert | W1 transpose | ph init ---------
// blocks [0, 2048):    X fp32 -> fp16 streaming convert (DRAM-bound, ~55us)
// blocks [2048, 3072): W1 [H,U] fp32 -> g_W1h [U,H] fp16 (rides in X window)
// blocks [3072, 3200): ph init (W1_b + W2_b) + zero g_score
__global__ void __launch_bounds__(256)
k_prep(const float* __restrict__ X, const float* __restrict__ W1,
       const float* __restrict__ W1b, const float* __restrict__ W2b) {
    __shared__ float t[32][33];
    const int bid = blockIdx.x;
    const int tid = threadIdx.x;

    if (bid < 2048) {
        size_t i = (size_t)bid * 256 + tid;   // float4 index
        const size_t stride = (size_t)2048 * 256;
        const size_t total = (size_t)MTOT * Hz / 4;
        for (; i < total; i += stride) {
            float4 v = *reinterpret_cast<const float4*>(X + i * 4);
            __half2 h0 = __floats2half2_rn(v.x, v.y);
            __half2 h1 = __floats2half2_rn(v.z, v.w);
            uint2 pk = make_uint2(*reinterpret_cast<uint32_t*>(&h0),
                                  *reinterpret_cast<uint32_t*>(&h1));
            *reinterpret_cast<uint2*>(g_Xh + i * 4) = pk;
        }
    } else if (bid < 3072) {
        const int b2 = bid - 2048;            // 0..1023
        const int u0 = (b2 & 31) * 32, h0 = (b2 >> 5) * 32;
        const int tx = tid & 31, ty = tid >> 5;   // 32 x 8
        #pragma unroll
        for (int j = 0; j < 32; j += 8)
            t[ty + j][tx] = W1[(size_t)(h0 + ty + j) * Uz + u0 + tx];
        __syncthreads();
        #pragma unroll
        for (int j = 0; j < 32; j += 8)
            g_W1h[(size_t)(u0 + ty + j) * Hz + h0 + tx] = __float2half(t[tx][ty + j]);
    } else {
        const int i = (bid - 3072) * 256 + tid;   // 0..32767
        const int u = i & (Uz - 1);
        g_ph[i] = W1b[u] + W2b[u];
        g_score[i] = 0.f;
        g_score[i + 32768] = 0.f;
    }
}

// ph[b][u] += sum_h lh[b][h] * W2[h][u]   (u-blocks of 64, h-slices of 16)
__global__ void k_ph(const float* __restrict__ lh, const float* __restrict__ W2) {
    __shared__ float lh_s[32][16];
    int u0 = blockIdx.x * 64, h0 = blockIdx.y * 16;
    int tid = threadIdx.x;
    for (int idx = tid; idx < 512; idx += 256) {
        int bb = idx >> 4, hh = idx & 15;
        lh_s[bb][hh] = lh[bb * Hz + h0 + hh];
    }
    __syncthreads();
    int u = u0 + (tid & 63);
    int bh = (tid >> 6) * 8;     // 4 groups x 8 batches
    float acc[8];
    #pragma unroll
    for (int i = 0; i < 8; ++i) acc[i] = 0.f;
    #pragma unroll
    for (int hh = 0; hh < 16; ++hh) {
        float w = W2[(size_t)(h0 + hh) * Uz + u];
        #pragma unroll
        for (int i = 0; i < 8; ++i) acc[i] += lh_s[bh + i][hh] * w;
    }
    #pragma unroll
    for (int i = 0; i < 8; ++i) atomicAdd(&g_ph[(bh + i) * Uz + u], acc[i]);
}

// ---------------- fused main: GEMM(HMMA) + tanh + V-dot ----------------
// Grid (8, 512): blockIdx.x = n-octant (128 cols), blockIdx.y = m-tile (128).
// 128 threads / 4 warps per CTA, warp grid (2m, 2n), warp tile 64 x 64.
// smem 100352 B -> TWO CTAs co-resident per SM: while one CTA barriers /
// runs its epilogue, the other's MMAs keep the tensor pipe busy.
// K = 1024 in 16 slices of 64, 3-stage cp.async pipeline.
// SMEM map (bytes):
//   [0   .. 512)     score_s (128 f32)
//   [512 .. 1024)    ph_s    (128 f32)
//   [1024.. 1536)    v_s     (128 f32)
//   [2048.. 51200)   X fp16  3 stages x [128 x 64] SW128 (16KB/stage)
//   [51200..100352)  W fp16  3 stages x [128 x 64] SW128 (16KB/stage)
#define SMEM_MAIN 100352

__global__ void __launch_bounds__(128, 2)
k_main(const float* __restrict__ Vw) {
    extern __shared__ char smem[];
    const uint32_t sb = smem_u32(smem);
    float* score_s = reinterpret_cast<float*>(smem);
    float* ph_s = reinterpret_cast<float*>(smem + 512);
    float* v_s = reinterpret_cast<float*>(smem + 1024);
    const uint32_t XS = sb + 2048;
    const uint32_t WS = sb + 51200;

    const int tid = threadIdx.x;
    const int wid = tid >> 5, l = tid & 31;
    const int wm = wid & 1, wn = wid >> 1;     // 2m x 2n warp grid
    const int m0 = blockIdx.y * 128;
    const int n0 = blockIdx.x * 128;
    const int b = m0 >> 11;                    // batch (2048 rows each)

    score_s[tid] = 0.f;
    ph_s[tid] = g_ph[b * Uz + n0 + tid];
    v_s[tid] = Vw[n0 + tid];

    // ldmatrix lane-invariant offset pieces
    const uint32_t a_row = (uint32_t)(wm * 64 + (l & 15));
    const uint32_t a_k16 = (uint32_t)(((l >> 4) & 1) * 16);
    const uint32_t b_row = (uint32_t)(wn * 64 + ((l >> 4) & 1) * 8 + (l & 7));
    const uint32_t b_k16 = (uint32_t)(((l >> 3) & 1) * 16);

    // cp.async pieces: X 1024 + W 1024 chunks of 16B, 128 threads
    const int cp_r = tid >> 3;            // row 0..15 base
    const int cp_c = tid & 7;             // 16B column 0..7

    float acc[4][8][4];
    #pragma unroll
    for (int mb = 0; mb < 4; ++mb)
        #pragma unroll
        for (int nb = 0; nb < 8; ++nb)
            #pragma unroll
            for (int i = 0; i < 4; ++i) acc[mb][nb][i] = 0.f;

    // ---- issue cp.async loads for slice s into stage s%3 ----
    auto load_slice = [&](int s) {
        const int st = s % 3;
        const int k0 = s * 64;
        const uint32_t xdst = XS + st * 16384;
        const uint32_t wdst = WS + st * 16384;
        const __half* xsrc = g_Xh + (size_t)m0 * Hz + k0;
        const __half* wsrc = g_W1h + (size_t)n0 * Hz + k0;
        #pragma unroll
        for (int i = 0; i < 8; ++i) {         // 128 rows each, 16 per pass
            int r = cp_r + i * 16;
            uint32_t dso = sw128((uint32_t)(r * 128 + cp_c * 16));
            size_t gx = __cvta_generic_to_global(xsrc + (size_t)r * Hz + cp_c * 8);
            size_t gw = __cvta_generic_to_global(wsrc + (size_t)r * Hz + cp_c * 8);
            asm volatile("cp.async.cg.shared.global [%0], [%1], 16;"
                         :: "r"(xdst + dso), "l"(gx));
            asm volatile("cp.async.cg.shared.global [%0], [%1], 16;"
                         :: "r"(wdst + dso), "l"(gw));
        }
        asm volatile("cp.async.commit_group;");
    };

    // prologue: fill 2 of 3 stages
    load_slice(0);
    load_slice(1);

    for (int s = 0; s < 16; ++s) {
        if (s < 15) asm volatile("cp.async.wait_group 1;");
        else        asm volatile("cp.async.wait_group 0;");
        __syncthreads();   // publish stage s; stage (s+2)%3 free

        if (s + 2 < 16) load_slice(s + 2);

        const uint32_t xb = XS + (s % 3) * 16384;
        const uint32_t wb = WS + (s % 3) * 16384;

        #pragma unroll
        for (int kk = 0; kk < 4; ++kk) {      // four k16 steps per 64-k slice
            uint32_t fa[4][4], fb[4][4];
            #pragma unroll
            for (int mb = 0; mb < 4; ++mb) {
                uint32_t off = (a_row + mb * 16) * 128 + kk * 32 + a_k16;
                LDSM_X4(fa[mb][0], fa[mb][1], fa[mb][2], fa[mb][3],
                        xb + sw128(off));
            }
            #pragma unroll
            for (int p = 0; p < 4; ++p) {
                uint32_t off = (b_row + p * 16) * 128 + kk * 32 + b_k16;
                LDSM_X4(fb[p][0], fb[p][1], fb[p][2], fb[p][3],
                        wb + sw128(off));
            }
            #pragma unroll
            for (int mb = 0; mb < 4; ++mb)
                #pragma unroll
                for (int nb = 0; nb < 8; ++nb)
                    MMA16816(acc[mb][nb], fa[mb],
                             fb[nb >> 1][(nb & 1) * 2],
                             fb[nb >> 1][(nb & 1) * 2 + 1]);
        }
    }

    // ---- epilogue: tanh(acc + ph) * v, reduce over the 128 n-cols ----
    const int t = l & 3, g = l >> 2;
    #pragma unroll
    for (int mb = 0; mb < 4; ++mb) {
        float rs0 = 0.f, rs1 = 0.f;
        #pragma unroll
        for (int nb = 0; nb < 8; ++nb) {
            int nl = wn * 64 + nb * 8 + t * 2;
            float p0 = ph_s[nl], v0 = v_s[nl];
            float p1 = ph_s[nl + 1], v1 = v_s[nl + 1];
            rs0 += tanh_fast(acc[mb][nb][0] + p0) * v0
                 + tanh_fast(acc[mb][nb][1] + p1) * v1;
            rs1 += tanh_fast(acc[mb][nb][2] + p0) * v0
                 + tanh_fast(acc[mb][nb][3] + p1) * v1;
        }
        rs0 += __shfl_xor_sync(0xffffffffu, rs0, 1);
        rs0 += __shfl_xor_sync(0xffffffffu, rs0, 2);
        rs1 += __shfl_xor_sync(0xffffffffu, rs1, 1);
        rs1 += __shfl_xor_sync(0xffffffffu, rs1, 2);
        if (t == 0) {
            int r0 = wm * 64 + mb * 16 + g;
            atomicAdd(&score_s[r0], rs0);
            atomicAdd(&score_s[r0 + 8], rs1);
        }
    }
    __syncthreads();

    atomicAdd(&g_score[m0 + tid], score_s[tid]);
}

// ---------------- softmax over S per batch ----------------
__global__ void k_softmax(float* __restrict__ out) {
    __shared__ float red[256];
    int b = blockIdx.x, tid = threadIdx.x;  // 256 threads, 8 elems each
    float v[8];
    float mx = -1e30f;
    #pragma unroll
    for (int i = 0; i < 8; ++i) {
        float x = g_score[b * Sz + tid + i * 256];
        v[i] = x;
        mx = fmaxf(mx, x);
    }
    red[tid] = mx;
    __syncthreads();
    for (int o = 128; o > 0; o >>= 1) {
        if (tid < o) red[tid] = fmaxf(red[tid], red[tid + o]);
        __syncthreads();
    }
    mx = red[0];
    __syncthreads();
    float sum = 0.f;
    #pragma unroll
    for (int i = 0; i < 8; ++i) { v[i] = expf(v[i] - mx); sum += v[i]; }
    red[tid] = sum;
    __syncthreads();
    for (int o = 128; o > 0; o >>= 1) {
        if (tid < o) red[tid] += red[tid + o];
        __syncthreads();
    }
    float tot = red[0];
    #pragma unroll
    for (int i = 0; i < 8; ++i)
        out[b * Sz + tid + i * 256] = v[i] / tot;
}

// ---------------- launch ----------------
extern "C" void kernel_launch(void* const* d_in, const int* in_sizes, int n_in,
                              void* d_out, int out_size) {
    const float* enc = (const float*)d_in[0];   // [B,S,H]
    const float* lh  = (const float*)d_in[1];   // [B,H]
    const float* W1  = (const float*)d_in[2];   // [H,U]
    const float* W1b = (const float*)d_in[3];   // [U]
    const float* W2  = (const float*)d_in[4];   // [H,U]
    const float* W2b = (const float*)d_in[5];   // [U]
    const float* Vw  = (const float*)d_in[6];   // [U,1]
    float* out = (float*)d_out;                  // [B,S,1]

    cudaFuncSetAttribute(k_main, cudaFuncAttributeMaxDynamicSharedMemorySize, SMEM_MAIN);

    k_prep<<<3200, 256>>>(enc, W1, W1b, W2b);
    k_ph<<<dim3(16, 64), 256>>>(lh, W2);
    k_main<<<dim3(8, 512), 128, SMEM_MAIN>>>(Vw);
    k_softmax<<<Bz, 256>>>(out);
}